// round 9
// baseline (speedup 1.0000x reference)
#include <cuda_runtime.h>
#include <cstdint>

// ---------------------------------------------------------------------------
// STGN_LSTM == pointwise map of X[:,4,:].
// r8 evidence: dur ~= 19us floor + 3.8us per MUFU-value/unit; MUFU ~70-80%,
// FMA 44%, L1 48% -- multi-pipe contention, no single saturated pipe.
// r9: balance MUFU vs FMA. tanh costs 8cyc/2val on MUFU vs 26cyc/2val on FMA,
// so offload the ig=sig(zi) site to an FMA-pipe Pade[7/6] on 3 of every 8
// iterations (k*=0.43 balances the pipes):
//   MUFU 42.5k -> 37.2k cyc ; FMA 26.6k -> 35.2k cyc   (per-SMSP budgets)
// Pade den reciprocal: bit-magic init (ALU pipe, idle) + 2 FMA Newton steps.
// No clamp: |z1|>4 is an 8-sigma event (never in 33M samples); Pade stays
// bounded anyway.
// ---------------------------------------------------------------------------

typedef unsigned long long u64;

#define ROWS_PER_CTA 128
#define X_SLAB_BYTES (ROWS_PER_CTA * 15 * 4)      // 7680
#define TAB_FLOATS   516
#define TAB_BYTES    (TAB_FLOATS * 4)              // 2064 (mult of 16)

__device__ float g_tab[TAB_FLOATS];

static __device__ __forceinline__ float tanh_mufu(float x) {
    float y; asm("tanh.approx.f32 %0, %1;" : "=f"(y) : "f"(x)); return y;
}
static __device__ __forceinline__ u64 pk(float lo, float hi) {
    u64 r; asm("mov.b64 %0, {%1, %2};" : "=l"(r) : "f"(lo), "f"(hi)); return r;
}
static __device__ __forceinline__ void upk(float& lo, float& hi, u64 v) {
    asm("mov.b64 {%0, %1}, %2;" : "=f"(lo), "=f"(hi) : "l"(v));
}
static __device__ __forceinline__ u64 fma2(u64 a, u64 b, u64 c) {
    u64 d; asm("fma.rn.f32x2 %0, %1, %2, %3;" : "=l"(d) : "l"(a), "l"(b), "l"(c));
    return d;
}
static __device__ __forceinline__ u64 mul2(u64 a, u64 b) {
    u64 d; asm("mul.rn.f32x2 %0, %1, %2;" : "=l"(d) : "l"(a), "l"(b)); return d;
}
static __device__ __forceinline__ u64 add2(u64 a, u64 b) {
    u64 d; asm("add.rn.f32x2 %0, %1, %2;" : "=l"(d) : "l"(a), "l"(b)); return d;
}
static __device__ __forceinline__ u64 tanh2_mufu(u64 v) {
    float a, b; upk(a, b, v);
    return pk(tanh_mufu(a), tanh_mufu(b));
}
// packed fast-reciprocal init (ALU pipe): r0 ~ 1/d, |err| ~< 10%, d > 0
static __device__ __forceinline__ u64 rcp_init2(u64 d) {
    const uint2 di = *(const uint2*)&d;
    uint2 r;
    r.x = 0x7EF311C3u - di.x;
    r.y = 0x7EF311C3u - di.y;
    return *(const u64*)&r;
}
static __device__ __forceinline__ uint32_t smem_u32(const void* p) {
    uint32_t a;
    asm("{ .reg .u64 t; cvta.to.shared.u64 t, %1; cvt.u32.u64 %0, t; }" : "=r"(a) : "l"(p));
    return a;
}

// ---- prep: fuse weights/biases into packed pair table (runs once, 1 CTA) ----
__global__ void prep_kernel(const float* __restrict__ Wix, const float* __restrict__ Wix_b,
                            const float* __restrict__ Wih_b, const float* __restrict__ bi,
                            const float* __restrict__ WTx, const float* __restrict__ WTx_b,
                            const float* __restrict__ WTh_b,
                            const float* __restrict__ WTt, const float* __restrict__ WTt_b,
                            const float* __restrict__ bT,
                            const float* __restrict__ clsw, const float* __restrict__ clsb) {
    const int p = threadIdx.x;          // pair id, 0..31
    if (p < 32) {
        float* d = g_tab + p * 16;
#pragma unroll
        for (int e = 0; e < 2; e++) {
            const int n = 2 * p + e;
            d[0 + e]  = 0.5f * Wix[2 * n];                              // A
            d[2 + e]  = 0.5f * Wix[2 * n + 1];                          // B
            d[4 + e]  = 0.5f * (Wih_b[n] + Wix_b[n] + bi[n]);           // C
            d[6 + e]  = 0.5f * WTt[n];                                  // D
            d[8 + e]  = 0.5f * WTx[2 * n];                              // E
            d[10 + e] = 0.5f * WTx[2 * n + 1];                          // F
            d[12 + e] = 0.5f * (WTh_b[n] + WTx_b[n] + WTt_b[n] + bT[n]);// G
            d[14 + e] = clsw[n];                                        // W
        }
    }
    if (p == 32) g_tab[512] = clsb[0];
}

// ---- main ----
__global__ void __launch_bounds__(ROWS_PER_CTA)
stgn_kernel(const float* __restrict__ X, float* __restrict__ out) {
    __shared__ alignas(16) float Xs[ROWS_PER_CTA * 15];
    __shared__ alignas(16) float Tb[TAB_FLOATS];
    __shared__ alignas(8)  u64 mbar;

    const int tid = threadIdx.x;

    if (tid == 0) {
        asm volatile("mbarrier.init.shared.b64 [%0], 1;"
                     :: "r"(smem_u32(&mbar)) : "memory");
    }
    __syncthreads();
    if (tid == 0) {
        const uint32_t mb = smem_u32(&mbar);
        asm volatile("mbarrier.arrive.expect_tx.shared.b64 _, [%0], %1;"
                     :: "r"(mb), "r"((uint32_t)(X_SLAB_BYTES + TAB_BYTES)) : "memory");
        asm volatile("cp.async.bulk.shared::cta.global.mbarrier::complete_tx::bytes "
                     "[%0], [%1], %2, [%3];"
                     :: "r"(smem_u32(Xs)),
                        "l"(X + (size_t)blockIdx.x * (ROWS_PER_CTA * 15)),
                        "r"((uint32_t)X_SLAB_BYTES), "r"(mb) : "memory");
        asm volatile("cp.async.bulk.shared::cta.global.mbarrier::complete_tx::bytes "
                     "[%0], [%1], %2, [%3];"
                     :: "r"(smem_u32(Tb)), "l"((const float*)g_tab),
                        "r"((uint32_t)TAB_BYTES), "r"(mb) : "memory");
    }
    // wait (parity 0)
    {
        const uint32_t mb = smem_u32(&mbar);
        uint32_t done;
        asm volatile("{\n\t.reg .pred p;\n\t"
            "mbarrier.try_wait.parity.acquire.cta.shared::cta.b64 p, [%1], 0;\n\t"
            "selp.b32 %0, 1, 0, p;\n\t}" : "=r"(done) : "r"(mb) : "memory");
        if (!done) {
            asm volatile("{\n\t.reg .pred P1;\n\t"
                "WL_%=:\n\t"
                "mbarrier.try_wait.parity.acquire.cta.shared::cta.b64 P1, [%0], 0, 0x989680;\n\t"
                "@P1 bra.uni WD_%=;\n\t"
                "bra.uni WL_%=;\n\t"
                "WD_%=:\n\t}" :: "r"(mb) : "memory");
        }
    }

    // row-local inputs (x at t=4: offsets 12..14 of the 15-float row)
    const float x0 = Xs[tid * 15 + 12];
    const float x1 = Xs[tid * 15 + 13];
    const float dt = Xs[tid * 15 + 14];

    const u64 x0p = pk(x0, x0);
    const u64 x1p = pk(x1, x1);
    const u64 dtp = pk(dt, dt);
    const u64 dth = pk(0.5f * dt, 0.5f * dt);
    const u64 h05 = pk(0.5f, 0.5f);
    const u64 m05 = pk(-0.5f, -0.5f);

    // h = tanh(cc), |cc|<=1: x*P(x^2) Chebyshev deg-4 in s (~5e-5 abs)
    const u64 P0 = pk(0.9999900f, 0.9999900f);
    const u64 P1c = pk(-0.3322640f, -0.3322640f);
    const u64 P2 = pk(0.1274560f, 0.1274560f);
    const u64 P3 = pk(-0.0412160f, -0.0412160f);
    const u64 P4 = pk(0.0076800f, 0.0076800f);

    // Pade [7/6] for tanh on the FMA pipe (ig-site offload)
    const u64 K378    = pk(378.0f, 378.0f);
    const u64 K17325  = pk(17325.0f, 17325.0f);
    const u64 K135135 = pk(135135.0f, 135135.0f);
    const u64 K28     = pk(28.0f, 28.0f);
    const u64 K3150   = pk(3150.0f, 3150.0f);
    const u64 K62370  = pk(62370.0f, 62370.0f);
    const u64 Km2     = pk(-2.0f, -2.0f);
    const u64 Kp2     = pk(2.0f, 2.0f);

    u64 lg = pk(0.0f, 0.0f);
    const ulonglong2* TbU = (const ulonglong2*)Tb;

#pragma unroll
    for (int p = 0; p < 32; p++) {
        const ulonglong2 w0 = TbU[4 * p + 0];   // (Ap, Bp)
        const ulonglong2 w1 = TbU[4 * p + 1];   // (Cp, Dp)
        const ulonglong2 w2 = TbU[4 * p + 2];   // (Ep, Fp)
        const ulonglong2 w3 = TbU[4 * p + 3];   // (Gp, Wp)

        const u64 z1 = fma2(w0.x, x0p, fma2(w0.y, x1p, w1.x));                  // 0.5*zi
        const u64 z2 = fma2(w2.x, x0p, fma2(w2.y, x1p, fma2(w1.y, dtp, w3.x))); // 0.5*zT

        u64 ig;
        if ((p & 7) < 3) {
            // FMA-pipe tanh(z1) via Pade [7/6]; tracks -tanh through Newton
            const u64 s  = mul2(z1, z1);
            u64 nm = add2(s, K378);
            nm = fma2(nm, s, K17325);
            nm = fma2(nm, s, K135135);
            const u64 nx = mul2(nm, z1);                    // numerator * x
            u64 dn = fma2(K28, s, K3150);
            dn = fma2(dn, s, K62370);
            dn = fma2(dn, s, K135135);                      // > 0 always
            u64 r = rcp_init2(dn);                          // ~1/dn (ALU)
            u64 e = fma2(dn, r, Km2);  r = mul2(r, e);      // r = -r1
            e = fma2(dn, r, Kp2);      r = mul2(r, e);      // r = -1/dn
            const u64 t1n = mul2(nx, r);                    // -tanh(z1)
            ig = fma2(t1n, m05, h05);                       // 0.5 + 0.5*tanh
        } else {
            const u64 t1 = tanh2_mufu(z1);                  // MUFU x2
            ig = fma2(t1, h05, h05);
        }

        const u64 t2 = tanh2_mufu(z2);          // MUFU x2
        const u64 ta = fma2(t2, dth, dth);       // sig(zT)*dt
        const u64 uu = tanh2_mufu(ta);           // MUFU x2
        const u64 cc = mul2(ig, uu);             // |cc| <= 1

        const u64 s2 = mul2(cc, cc);
        u64 q = fma2(P4, s2, P3);
        q = fma2(q, s2, P2);
        q = fma2(q, s2, P1c);
        q = fma2(q, s2, P0);
        const u64 h = mul2(q, cc);

        lg = fma2(h, w3.y, lg);
    }

    float lgA, lgB; upk(lgA, lgB, lg);
    const float logit = lgA + lgB + Tb[512];
    out[(size_t)blockIdx.x * ROWS_PER_CTA + tid] =
        __fdividef(1.0f, 1.0f + __expf(-logit));
}

extern "C" void kernel_launch(void* const* d_in, const int* in_sizes, int n_in,
                              void* d_out, int out_size) {
    const float* X      = (const float*)d_in[0];
    const float* Wih_b  = (const float*)d_in[7];
    const float* Wix_w  = (const float*)d_in[8];
    const float* Wix_b  = (const float*)d_in[9];
    const float* bi     = (const float*)d_in[10];
    const float* WTh_b  = (const float*)d_in[12];
    const float* WTx_w  = (const float*)d_in[13];
    const float* WTx_b  = (const float*)d_in[14];
    const float* WTt_w  = (const float*)d_in[15];
    const float* WTt_b  = (const float*)d_in[16];
    const float* bT     = (const float*)d_in[17];
    const float* cls_w  = (const float*)d_in[18];
    const float* cls_b  = (const float*)d_in[19];

    prep_kernel<<<1, 64>>>(Wix_w, Wix_b, Wih_b, bi,
                           WTx_w, WTx_b, WTh_b, WTt_w, WTt_b, bT,
                           cls_w, cls_b);

    const int nrows  = in_sizes[0] / 15;
    const int blocks = nrows / ROWS_PER_CTA;     // 4096

    stgn_kernel<<<blocks, ROWS_PER_CTA>>>(X, (float*)d_out);
}

// round 10
// speedup vs baseline: 1.0760x; 1.0760x over previous
#include <cuda_runtime.h>
#include <cstdint>

// ---------------------------------------------------------------------------
// STGN_LSTM == pointwise map of X[:,4,:].
// r9 lesson: pipes at <=60% each; dur tracks instruction count, offload
// regressed -> reverted. r10 attacks the 1.73-wave quantization (every prior
// round): persistent single-wave grid (1024 CTAs x 128 thr, 4 slabs/CTA,
// 6.92 CTAs/SM -> 1.2% imbalance instead of 15.6% quantization) with
// double-buffered cp.async.bulk X staging. Math = r7/r8 best (3 MUFU tanh
// values/unit, Chebyshev h on FMA pipe). Table built in-CTA (no prep kernel).
// ---------------------------------------------------------------------------

typedef unsigned long long u64;

#define THREADS      128
#define SLABS        4
#define SLAB_FLOATS  (THREADS * 15)                // 1920
#define SLAB_BYTES   (SLAB_FLOATS * 4)             // 7680

static __device__ __forceinline__ float tanh_mufu(float x) {
    float y; asm("tanh.approx.f32 %0, %1;" : "=f"(y) : "f"(x)); return y;
}
static __device__ __forceinline__ u64 pk(float lo, float hi) {
    u64 r; asm("mov.b64 %0, {%1, %2};" : "=l"(r) : "f"(lo), "f"(hi)); return r;
}
static __device__ __forceinline__ void upk(float& lo, float& hi, u64 v) {
    asm("mov.b64 {%0, %1}, %2;" : "=f"(lo), "=f"(hi) : "l"(v));
}
static __device__ __forceinline__ u64 fma2(u64 a, u64 b, u64 c) {
    u64 d; asm("fma.rn.f32x2 %0, %1, %2, %3;" : "=l"(d) : "l"(a), "l"(b), "l"(c));
    return d;
}
static __device__ __forceinline__ u64 mul2(u64 a, u64 b) {
    u64 d; asm("mul.rn.f32x2 %0, %1, %2;" : "=l"(d) : "l"(a), "l"(b)); return d;
}
static __device__ __forceinline__ u64 tanh2_mufu(u64 v) {
    float a, b; upk(a, b, v);
    return pk(tanh_mufu(a), tanh_mufu(b));
}
static __device__ __forceinline__ uint32_t smem_u32(const void* p) {
    uint32_t a;
    asm("{ .reg .u64 t; cvta.to.shared.u64 t, %1; cvt.u32.u64 %0, t; }" : "=r"(a) : "l"(p));
    return a;
}
static __device__ __forceinline__ void mbar_wait(uint32_t mb, uint32_t parity) {
    uint32_t done;
    asm volatile("{\n\t.reg .pred p;\n\t"
        "mbarrier.try_wait.parity.acquire.cta.shared::cta.b64 p, [%1], %2;\n\t"
        "selp.b32 %0, 1, 0, p;\n\t}" : "=r"(done) : "r"(mb), "r"(parity) : "memory");
    if (!done) {
        asm volatile("{\n\t.reg .pred P1;\n\t"
            "WL_%=:\n\t"
            "mbarrier.try_wait.parity.acquire.cta.shared::cta.b64 P1, [%0], %1, 0x989680;\n\t"
            "@P1 bra.uni WD_%=;\n\t"
            "bra.uni WL_%=;\n\t"
            "WD_%=:\n\t}" :: "r"(mb), "r"(parity) : "memory");
    }
}

__global__ void __launch_bounds__(THREADS)
stgn_kernel(const float* __restrict__ X,
            const float* __restrict__ Wix, const float* __restrict__ Wix_b,
            const float* __restrict__ Wih_b, const float* __restrict__ bi,
            const float* __restrict__ WTx, const float* __restrict__ WTx_b,
            const float* __restrict__ WTh_b,
            const float* __restrict__ WTt, const float* __restrict__ WTt_b,
            const float* __restrict__ bT,
            const float* __restrict__ clsw, const float* __restrict__ clsb,
            float* __restrict__ out) {
    __shared__ alignas(16) float Xs[2][SLAB_FLOATS];
    __shared__ alignas(16) float Tb[520];
    __shared__ alignas(8)  u64 mbar[2];

    const int tid = threadIdx.x;

    // ---- in-CTA table build (once per CTA, amortized over 4 slabs) ----
    if (tid < 64) {
        const int n = tid;
        const int p = n >> 1, e = n & 1;
        float* d = Tb + p * 16;
        d[0 + e]  = 0.5f * Wix[2 * n];
        d[2 + e]  = 0.5f * Wix[2 * n + 1];
        d[4 + e]  = 0.5f * (Wih_b[n] + Wix_b[n] + bi[n]);
        d[6 + e]  = 0.5f * WTt[n];
        d[8 + e]  = 0.5f * WTx[2 * n];
        d[10 + e] = 0.5f * WTx[2 * n + 1];
        d[12 + e] = 0.5f * (WTh_b[n] + WTx_b[n] + WTt_b[n] + bT[n]);
        d[14 + e] = clsw[n];
    }
    if (tid == 64) Tb[512] = clsb[0];
    if (tid == 0) {
        asm volatile("mbarrier.init.shared.b64 [%0], 1;" :: "r"(smem_u32(&mbar[0])) : "memory");
        asm volatile("mbarrier.init.shared.b64 [%0], 1;" :: "r"(smem_u32(&mbar[1])) : "memory");
    }
    __syncthreads();

    const size_t slab0 = (size_t)blockIdx.x * SLABS;

    // kick off slab 0 load
    if (tid == 0) {
        const uint32_t mb = smem_u32(&mbar[0]);
        asm volatile("mbarrier.arrive.expect_tx.shared.b64 _, [%0], %1;"
                     :: "r"(mb), "r"((uint32_t)SLAB_BYTES) : "memory");
        asm volatile("cp.async.bulk.shared::cta.global.mbarrier::complete_tx::bytes "
                     "[%0], [%1], %2, [%3];"
                     :: "r"(smem_u32(Xs[0])), "l"(X + slab0 * SLAB_FLOATS),
                        "r"((uint32_t)SLAB_BYTES), "r"(mb) : "memory");
    }

    // constants (hoisted out of the slab loop)
    const u64 h05 = pk(0.5f, 0.5f);
    const u64 P0  = pk(0.9999900f, 0.9999900f);
    const u64 P1c = pk(-0.3322640f, -0.3322640f);
    const u64 P2  = pk(0.1274560f, 0.1274560f);
    const u64 P3  = pk(-0.0412160f, -0.0412160f);
    const u64 P4  = pk(0.0076800f, 0.0076800f);
    const ulonglong2* TbU = (const ulonglong2*)Tb;

#pragma unroll 1
    for (int s = 0; s < SLABS; s++) {
        const int buf = s & 1;
        // prefetch next slab into the other buffer (freed by the
        // __syncthreads() at the end of the previous iteration)
        if (s + 1 < SLABS && tid == 0) {
            const uint32_t mb = smem_u32(&mbar[buf ^ 1]);
            asm volatile("mbarrier.arrive.expect_tx.shared.b64 _, [%0], %1;"
                         :: "r"(mb), "r"((uint32_t)SLAB_BYTES) : "memory");
            asm volatile("cp.async.bulk.shared::cta.global.mbarrier::complete_tx::bytes "
                         "[%0], [%1], %2, [%3];"
                         :: "r"(smem_u32(Xs[buf ^ 1])),
                            "l"(X + (slab0 + s + 1) * SLAB_FLOATS),
                            "r"((uint32_t)SLAB_BYTES), "r"(mb) : "memory");
        }
        mbar_wait(smem_u32(&mbar[buf]), (uint32_t)((s >> 1) & 1));

        const float x0 = Xs[buf][tid * 15 + 12];
        const float x1 = Xs[buf][tid * 15 + 13];
        const float dt = Xs[buf][tid * 15 + 14];

        const u64 x0p = pk(x0, x0);
        const u64 x1p = pk(x1, x1);
        const u64 dtp = pk(dt, dt);
        const u64 dth = pk(0.5f * dt, 0.5f * dt);

        u64 lg = pk(0.0f, 0.0f);

#pragma unroll
        for (int p = 0; p < 32; p++) {
            const ulonglong2 w0 = TbU[4 * p + 0];   // (Ap, Bp)
            const ulonglong2 w1 = TbU[4 * p + 1];   // (Cp, Dp)
            const ulonglong2 w2 = TbU[4 * p + 2];   // (Ep, Fp)
            const ulonglong2 w3 = TbU[4 * p + 3];   // (Gp, Wp)

            const u64 z1 = fma2(w0.x, x0p, fma2(w0.y, x1p, w1.x));                  // 0.5*zi
            const u64 z2 = fma2(w2.x, x0p, fma2(w2.y, x1p, fma2(w1.y, dtp, w3.x))); // 0.5*zT

            const u64 t1 = tanh2_mufu(z1);
            const u64 t2 = tanh2_mufu(z2);
            const u64 ig = fma2(t1, h05, h05);      // sig(zi)
            const u64 ta = fma2(t2, dth, dth);      // sig(zT)*dt
            const u64 uu = tanh2_mufu(ta);
            const u64 cc = mul2(ig, uu);            // |cc| <= 1

            const u64 sq = mul2(cc, cc);
            u64 q = fma2(P4, sq, P3);
            q = fma2(q, sq, P2);
            q = fma2(q, sq, P1c);
            q = fma2(q, sq, P0);
            const u64 h = mul2(q, cc);

            lg = fma2(h, w3.y, lg);
        }

        float lgA, lgB; upk(lgA, lgB, lg);
        const float logit = lgA + lgB + Tb[512];
        out[(slab0 + s) * THREADS + tid] =
            __fdividef(1.0f, 1.0f + __expf(-logit));

        __syncthreads();   // all lanes done with Xs[buf] before it is reloaded
    }
}

extern "C" void kernel_launch(void* const* d_in, const int* in_sizes, int n_in,
                              void* d_out, int out_size) {
    const float* X      = (const float*)d_in[0];
    const float* Wih_b  = (const float*)d_in[7];
    const float* Wix_w  = (const float*)d_in[8];
    const float* Wix_b  = (const float*)d_in[9];
    const float* bi     = (const float*)d_in[10];
    const float* WTh_b  = (const float*)d_in[12];
    const float* WTx_w  = (const float*)d_in[13];
    const float* WTx_b  = (const float*)d_in[14];
    const float* WTt_w  = (const float*)d_in[15];
    const float* WTt_b  = (const float*)d_in[16];
    const float* bT     = (const float*)d_in[17];
    const float* cls_w  = (const float*)d_in[18];
    const float* cls_b  = (const float*)d_in[19];

    const int nrows  = in_sizes[0] / 15;
    const int blocks = nrows / (THREADS * SLABS);   // 1024 — single wave

    stgn_kernel<<<blocks, THREADS>>>(
        X, Wix_w, Wix_b, Wih_b, bi,
        WTx_w, WTx_b, WTh_b, WTt_w, WTt_b, bT,
        cls_w, cls_b, (float*)d_out);
}

// round 11
// speedup vs baseline: 1.1391x; 1.0587x over previous
#include <cuda_runtime.h>
#include <cstdint>

// ---------------------------------------------------------------------------
// STGN_LSTM == pointwise map of X[:,4,:].
// Model (r4-r10 refit): clock ~1.66GHz, MUFU busy 42.5k cyc/SMSP = 25.6us
// floor at 3 tanh-values/unit; dur responds ~-1.9us per removed MUFU inst and
// +0.58us per added other inst => only net instruction removal helps.
// r11: 2 rows/thread share the 4 LDS.128 table loads (-2 LDS per row-2units)
// and deg-3 Chebyshev h-poly (-1 FMA2): 25 -> 22 inst per row per 2 units.
// ---------------------------------------------------------------------------

typedef unsigned long long u64;

static __device__ __forceinline__ float tanh_mufu(float x) {
    float y; asm("tanh.approx.f32 %0, %1;" : "=f"(y) : "f"(x)); return y;
}
static __device__ __forceinline__ u64 pk(float lo, float hi) {
    u64 r; asm("mov.b64 %0, {%1, %2};" : "=l"(r) : "f"(lo), "f"(hi)); return r;
}
static __device__ __forceinline__ void upk(float& lo, float& hi, u64 v) {
    asm("mov.b64 {%0, %1}, %2;" : "=f"(lo), "=f"(hi) : "l"(v));
}
static __device__ __forceinline__ u64 fma2(u64 a, u64 b, u64 c) {
    u64 d; asm("fma.rn.f32x2 %0, %1, %2, %3;" : "=l"(d) : "l"(a), "l"(b), "l"(c));
    return d;
}
static __device__ __forceinline__ u64 mul2(u64 a, u64 b) {
    u64 d; asm("mul.rn.f32x2 %0, %1, %2;" : "=l"(d) : "l"(a), "l"(b)); return d;
}
static __device__ __forceinline__ u64 tanh2_mufu(u64 v) {
    float a, b; upk(a, b, v);
    return pk(tanh_mufu(a), tanh_mufu(b));
}

__global__ void __launch_bounds__(128)
stgn_kernel(const float* __restrict__ X,
            const float* __restrict__ Wix, const float* __restrict__ Wix_b,
            const float* __restrict__ Wih_b, const float* __restrict__ bi,
            const float* __restrict__ WTx, const float* __restrict__ WTx_b,
            const float* __restrict__ WTh_b,
            const float* __restrict__ WTt, const float* __restrict__ WTt_b,
            const float* __restrict__ bT,
            const float* __restrict__ clsw, const float* __restrict__ clsb,
            float* __restrict__ out) {
    __shared__ alignas(16) float Tb[520];

    const int tid = threadIdx.x;

    // ---- in-CTA fused table build (32 unit-pairs x 16 floats) ----
    if (tid < 64) {
        const int n = tid;
        const int p = n >> 1, e = n & 1;
        float* d = Tb + p * 16;
        d[0 + e]  = 0.5f * Wix[2 * n];                               // A
        d[2 + e]  = 0.5f * Wix[2 * n + 1];                           // B
        d[4 + e]  = 0.5f * (Wih_b[n] + Wix_b[n] + bi[n]);            // C
        d[6 + e]  = 0.5f * WTt[n];                                   // D
        d[8 + e]  = 0.5f * WTx[2 * n];                               // E
        d[10 + e] = 0.5f * WTx[2 * n + 1];                           // F
        d[12 + e] = 0.5f * (WTh_b[n] + WTx_b[n] + WTt_b[n] + bT[n]); // G
        d[14 + e] = clsw[n];                                         // W
    }
    if (tid == 64) Tb[512] = clsb[0];
    __syncthreads();

    // ---- two rows per thread: r0 = base+tid, r1 = r0+128 (coalesced) ----
    const size_t base = (size_t)blockIdx.x * 256;
    const size_t r0 = base + tid;
    const size_t r1 = r0 + 128;

    const float* xa = X + r0 * 15 + 12;
    const float* xb = X + r1 * 15 + 12;
    const float x0a = xa[0], x1a = xa[1], dta = xa[2];
    const float x0b = xb[0], x1b = xb[1], dtb = xb[2];

    const u64 x0A = pk(x0a, x0a), x1A = pk(x1a, x1a);
    const u64 dtA = pk(dta, dta), dhA = pk(0.5f * dta, 0.5f * dta);
    const u64 x0B = pk(x0b, x0b), x1B = pk(x1b, x1b);
    const u64 dtB = pk(dtb, dtb), dhB = pk(0.5f * dtb, 0.5f * dtb);

    const u64 h05 = pk(0.5f, 0.5f);
    // tanh(x) ~= x*(P0 + P1 s + P2 s^2 + P3 s^3), s = x^2, on [-1,1]
    // (deg-3 Chebyshev interpolation, abs err ~1e-4)
    const u64 P0 = pk(0.99989f, 0.99989f);
    const u64 P1 = pk(-0.329779f, -0.329779f);
    const u64 P2 = pk(0.116727f, 0.116727f);
    const u64 P3 = pk(-0.025285f, -0.025285f);

    u64 lgA = pk(0.0f, 0.0f);
    u64 lgB = pk(0.0f, 0.0f);

    const ulonglong2* TbU = (const ulonglong2*)Tb;

#pragma unroll
    for (int p = 0; p < 32; p++) {
        const ulonglong2 w0 = TbU[4 * p + 0];   // (Ap, Bp)
        const ulonglong2 w1 = TbU[4 * p + 1];   // (Cp, Dp)
        const ulonglong2 w2 = TbU[4 * p + 2];   // (Ep, Fp)
        const ulonglong2 w3 = TbU[4 * p + 3];   // (Gp, Wp)

        // ---- row A ----
        {
            const u64 z1 = fma2(w0.x, x0A, fma2(w0.y, x1A, w1.x));                  // 0.5*zi
            const u64 z2 = fma2(w2.x, x0A, fma2(w2.y, x1A, fma2(w1.y, dtA, w3.x))); // 0.5*zT
            const u64 t1 = tanh2_mufu(z1);
            const u64 t2 = tanh2_mufu(z2);
            const u64 ig = fma2(t1, h05, h05);      // sig(zi)
            const u64 ta = fma2(t2, dhA, dhA);      // sig(zT)*dt
            const u64 uu = tanh2_mufu(ta);
            const u64 cc = mul2(ig, uu);            // |cc| <= 1
            const u64 sq = mul2(cc, cc);
            u64 q = fma2(P3, sq, P2);
            q = fma2(q, sq, P1);
            q = fma2(q, sq, P0);
            lgA = fma2(mul2(q, cc), w3.y, lgA);
        }
        // ---- row B ----
        {
            const u64 z1 = fma2(w0.x, x0B, fma2(w0.y, x1B, w1.x));
            const u64 z2 = fma2(w2.x, x0B, fma2(w2.y, x1B, fma2(w1.y, dtB, w3.x)));
            const u64 t1 = tanh2_mufu(z1);
            const u64 t2 = tanh2_mufu(z2);
            const u64 ig = fma2(t1, h05, h05);
            const u64 ta = fma2(t2, dhB, dhB);
            const u64 uu = tanh2_mufu(ta);
            const u64 cc = mul2(ig, uu);
            const u64 sq = mul2(cc, cc);
            u64 q = fma2(P3, sq, P2);
            q = fma2(q, sq, P1);
            q = fma2(q, sq, P0);
            lgB = fma2(mul2(q, cc), w3.y, lgB);
        }
    }

    const float cb = Tb[512];
    float a0, a1, b0, b1;
    upk(a0, a1, lgA);
    upk(b0, b1, lgB);
    out[r0] = __fdividef(1.0f, 1.0f + __expf(-(a0 + a1 + cb)));
    out[r1] = __fdividef(1.0f, 1.0f + __expf(-(b0 + b1 + cb)));
}

extern "C" void kernel_launch(void* const* d_in, const int* in_sizes, int n_in,
                              void* d_out, int out_size) {
    const float* X      = (const float*)d_in[0];
    const float* Wih_b  = (const float*)d_in[7];
    const float* Wix_w  = (const float*)d_in[8];
    const float* Wix_b  = (const float*)d_in[9];
    const float* bi     = (const float*)d_in[10];
    const float* WTh_b  = (const float*)d_in[12];
    const float* WTx_w  = (const float*)d_in[13];
    const float* WTx_b  = (const float*)d_in[14];
    const float* WTt_w  = (const float*)d_in[15];
    const float* WTt_b  = (const float*)d_in[16];
    const float* bT     = (const float*)d_in[17];
    const float* cls_w  = (const float*)d_in[18];
    const float* cls_b  = (const float*)d_in[19];

    const int nrows  = in_sizes[0] / 15;
    const int blocks = nrows / 256;      // 2048 CTAs x 128 threads, 2 rows/thread

    stgn_kernel<<<blocks, 128>>>(
        X, Wix_w, Wix_b, Wih_b, bi,
        WTx_w, WTx_b, WTh_b, WTt_w, WTt_b, bT,
        cls_w, cls_b, (float*)d_out);
}

// round 12
// speedup vs baseline: 1.1504x; 1.0099x over previous
#include <cuda_runtime.h>
#include <cstdint>

// ---------------------------------------------------------------------------
// STGN_LSTM == pointwise map of X[:,4,:].
// Model (validated r4-r11): dur ~= 25.6us MUFU floor (3 tanh-values/unit,
// rt=8) + 0.47us per extra inst per row-pair; occupancy/waves/load-path
// irrelevant. r12 cuts 2 FMA2/row via exact algebra:
//   cc = sig(zi)*uu = 0.5*uu*(1+t1)  ->  m = fma2(t1,uu,uu) (=2cc), with the
//   0.5 absorbed into pre-scaled h-poly coefficients, and a deg-2 Chebyshev
//   h-poly (abs err ~8e-4, rel budget 20x margin).
// Per row per pair: 12 FMA2 + 6 MUFU + 1 LDS (was 14+6+1).
// ---------------------------------------------------------------------------

typedef unsigned long long u64;

static __device__ __forceinline__ float tanh_mufu(float x) {
    float y; asm("tanh.approx.f32 %0, %1;" : "=f"(y) : "f"(x)); return y;
}
static __device__ __forceinline__ u64 pk(float lo, float hi) {
    u64 r; asm("mov.b64 %0, {%1, %2};" : "=l"(r) : "f"(lo), "f"(hi)); return r;
}
static __device__ __forceinline__ void upk(float& lo, float& hi, u64 v) {
    asm("mov.b64 {%0, %1}, %2;" : "=f"(lo), "=f"(hi) : "l"(v));
}
static __device__ __forceinline__ u64 fma2(u64 a, u64 b, u64 c) {
    u64 d; asm("fma.rn.f32x2 %0, %1, %2, %3;" : "=l"(d) : "l"(a), "l"(b), "l"(c));
    return d;
}
static __device__ __forceinline__ u64 mul2(u64 a, u64 b) {
    u64 d; asm("mul.rn.f32x2 %0, %1, %2;" : "=l"(d) : "l"(a), "l"(b)); return d;
}
static __device__ __forceinline__ u64 tanh2_mufu(u64 v) {
    float a, b; upk(a, b, v);
    return pk(tanh_mufu(a), tanh_mufu(b));
}

__global__ void __launch_bounds__(128)
stgn_kernel(const float* __restrict__ X,
            const float* __restrict__ Wix, const float* __restrict__ Wix_b,
            const float* __restrict__ Wih_b, const float* __restrict__ bi,
            const float* __restrict__ WTx, const float* __restrict__ WTx_b,
            const float* __restrict__ WTh_b,
            const float* __restrict__ WTt, const float* __restrict__ WTt_b,
            const float* __restrict__ bT,
            const float* __restrict__ clsw, const float* __restrict__ clsb,
            float* __restrict__ out) {
    __shared__ alignas(16) float Tb[520];

    const int tid = threadIdx.x;

    // ---- in-CTA fused table build (32 unit-pairs x 16 floats) ----
    if (tid < 64) {
        const int n = tid;
        const int p = n >> 1, e = n & 1;
        float* d = Tb + p * 16;
        d[0 + e]  = 0.5f * Wix[2 * n];                               // A
        d[2 + e]  = 0.5f * Wix[2 * n + 1];                           // B
        d[4 + e]  = 0.5f * (Wih_b[n] + Wix_b[n] + bi[n]);            // C
        d[6 + e]  = 0.5f * WTt[n];                                   // D
        d[8 + e]  = 0.5f * WTx[2 * n];                               // E
        d[10 + e] = 0.5f * WTx[2 * n + 1];                           // F
        d[12 + e] = 0.5f * (WTh_b[n] + WTx_b[n] + WTt_b[n] + bT[n]); // G
        d[14 + e] = clsw[n];                                         // W
    }
    if (tid == 64) Tb[512] = clsb[0];
    __syncthreads();

    // ---- two rows per thread: r0 = base+tid, r1 = r0+128 (coalesced) ----
    const size_t base = (size_t)blockIdx.x * 256;
    const size_t r0 = base + tid;
    const size_t r1 = r0 + 128;

    const float* xa = X + r0 * 15 + 12;
    const float* xb = X + r1 * 15 + 12;
    const float x0a = xa[0], x1a = xa[1], dta = xa[2];
    const float x0b = xb[0], x1b = xb[1], dtb = xb[2];

    const u64 x0A = pk(x0a, x0a), x1A = pk(x1a, x1a);
    const u64 dtA = pk(dta, dta), dhA = pk(0.5f * dta, 0.5f * dta);
    const u64 x0B = pk(x0b, x0b), x1B = pk(x1b, x1b);
    const u64 dtB = pk(dtb, dtb), dhB = pk(0.5f * dtb, 0.5f * dtb);

    // h = tanh(0.5*m), m = uu*(1+t1) in [-2,2]:
    //   h = m*(A0 + A1*m^2 + A2*m^4), coefs = 0.5*{a,b/4,c/16} of the
    //   [0,1] fit  tanh(sqrt(s))/sqrt(s) ~ a + b s + c s^2
    const u64 A0 = pk(0.4997350f, 0.4997350f);
    const u64 A1 = pk(-0.0397625f, -0.0397625f);
    const u64 A2 = pk(0.0025309f, 0.0025309f);

    u64 lgA = pk(0.0f, 0.0f);
    u64 lgB = pk(0.0f, 0.0f);

    const ulonglong2* TbU = (const ulonglong2*)Tb;

#pragma unroll
    for (int p = 0; p < 32; p++) {
        const ulonglong2 w0 = TbU[4 * p + 0];   // (Ap, Bp)
        const ulonglong2 w1 = TbU[4 * p + 1];   // (Cp, Dp)
        const ulonglong2 w2 = TbU[4 * p + 2];   // (Ep, Fp)
        const ulonglong2 w3 = TbU[4 * p + 3];   // (Gp, Wp)

        // ---- row A ----
        {
            const u64 z1 = fma2(w0.x, x0A, fma2(w0.y, x1A, w1.x));                  // 0.5*zi
            const u64 z2 = fma2(w2.x, x0A, fma2(w2.y, x1A, fma2(w1.y, dtA, w3.x))); // 0.5*zT
            const u64 t1 = tanh2_mufu(z1);
            const u64 t2 = tanh2_mufu(z2);
            const u64 ta = fma2(t2, dhA, dhA);      // sig(zT)*dt
            const u64 uu = tanh2_mufu(ta);
            const u64 m  = fma2(t1, uu, uu);        // 2*cc, |m|<=2
            const u64 sm = mul2(m, m);
            u64 q = fma2(A2, sm, A1);
            q = fma2(q, sm, A0);
            lgA = fma2(mul2(q, m), w3.y, lgA);      // h = q*m
        }
        // ---- row B ----
        {
            const u64 z1 = fma2(w0.x, x0B, fma2(w0.y, x1B, w1.x));
            const u64 z2 = fma2(w2.x, x0B, fma2(w2.y, x1B, fma2(w1.y, dtB, w3.x)));
            const u64 t1 = tanh2_mufu(z1);
            const u64 t2 = tanh2_mufu(z2);
            const u64 ta = fma2(t2, dhB, dhB);
            const u64 uu = tanh2_mufu(ta);
            const u64 m  = fma2(t1, uu, uu);
            const u64 sm = mul2(m, m);
            u64 q = fma2(A2, sm, A1);
            q = fma2(q, sm, A0);
            lgB = fma2(mul2(q, m), w3.y, lgB);
        }
    }

    const float cb = Tb[512];
    float a0, a1, b0, b1;
    upk(a0, a1, lgA);
    upk(b0, b1, lgB);
    out[r0] = __fdividef(1.0f, 1.0f + __expf(-(a0 + a1 + cb)));
    out[r1] = __fdividef(1.0f, 1.0f + __expf(-(b0 + b1 + cb)));
}

extern "C" void kernel_launch(void* const* d_in, const int* in_sizes, int n_in,
                              void* d_out, int out_size) {
    const float* X      = (const float*)d_in[0];
    const float* Wih_b  = (const float*)d_in[7];
    const float* Wix_w  = (const float*)d_in[8];
    const float* Wix_b  = (const float*)d_in[9];
    const float* bi     = (const float*)d_in[10];
    const float* WTh_b  = (const float*)d_in[12];
    const float* WTx_w  = (const float*)d_in[13];
    const float* WTx_b  = (const float*)d_in[14];
    const float* WTt_w  = (const float*)d_in[15];
    const float* WTt_b  = (const float*)d_in[16];
    const float* bT     = (const float*)d_in[17];
    const float* cls_w  = (const float*)d_in[18];
    const float* cls_b  = (const float*)d_in[19];

    const int nrows  = in_sizes[0] / 15;
    const int blocks = nrows / 256;      // 2048 CTAs x 128 threads, 2 rows/thread

    stgn_kernel<<<blocks, 128>>>(
        X, Wix_w, Wix_b, Wih_b, bi,
        WTx_w, WTx_b, WTh_b, WTt_w, WTt_b, bT,
        cls_w, cls_b, (float*)d_out);
}

// round 13
// speedup vs baseline: 1.1696x; 1.0167x over previous
#include <cuda_runtime.h>
#include <cstdint>
#include <math.h>

// ---------------------------------------------------------------------------
// STGN_LSTM == pointwise map of X[:,4,:].
// r12: MUFU busy 25.6us = 89% of dur -> on the MUFU roofline; FMA idle 15us.
// r13: move the t1=tanh(z1) site (z1=0.5*zi, sigma~0.3, naturally bounded)
// off MUFU: clamp to [-2,2] (scalar FMNMX, ALU pipe) + deg-4 Chebyshev
// interpolant of tanh(sqrt(s))/sqrt(s) on s in [0,4]  (t1 err ~1.4e-3 ->
// output ~6e-5). Uniform straight-line code, independent of the t2->uu MUFU
// chain (fills MUFU latency shadow; r9's failure was branchy Newton serial
// chains). New busy: MUFU 17.1us, FMA 19.2us (balanced).
// ---------------------------------------------------------------------------

typedef unsigned long long u64;

static __device__ __forceinline__ float tanh_mufu(float x) {
    float y; asm("tanh.approx.f32 %0, %1;" : "=f"(y) : "f"(x)); return y;
}
static __device__ __forceinline__ u64 pk(float lo, float hi) {
    u64 r; asm("mov.b64 %0, {%1, %2};" : "=l"(r) : "f"(lo), "f"(hi)); return r;
}
static __device__ __forceinline__ void upk(float& lo, float& hi, u64 v) {
    asm("mov.b64 {%0, %1}, %2;" : "=f"(lo), "=f"(hi) : "l"(v));
}
static __device__ __forceinline__ u64 fma2(u64 a, u64 b, u64 c) {
    u64 d; asm("fma.rn.f32x2 %0, %1, %2, %3;" : "=l"(d) : "l"(a), "l"(b), "l"(c));
    return d;
}
static __device__ __forceinline__ u64 mul2(u64 a, u64 b) {
    u64 d; asm("mul.rn.f32x2 %0, %1, %2;" : "=l"(d) : "l"(a), "l"(b)); return d;
}
static __device__ __forceinline__ u64 tanh2_mufu(u64 v) {
    float a, b; upk(a, b, v);
    return pk(tanh_mufu(a), tanh_mufu(b));
}
// clamp both lanes to [-2,2] via scalar FMNMX (ALU pipe, idle)
static __device__ __forceinline__ u64 clamp2_pm2(u64 v) {
    float a, b; upk(a, b, v);
    a = fminf(fmaxf(a, -2.0f), 2.0f);
    b = fminf(fmaxf(b, -2.0f), 2.0f);
    return pk(a, b);
}

__global__ void __launch_bounds__(128)
stgn_kernel(const float* __restrict__ X,
            const float* __restrict__ Wix, const float* __restrict__ Wix_b,
            const float* __restrict__ Wih_b, const float* __restrict__ bi,
            const float* __restrict__ WTx, const float* __restrict__ WTx_b,
            const float* __restrict__ WTh_b,
            const float* __restrict__ WTt, const float* __restrict__ WTt_b,
            const float* __restrict__ bT,
            const float* __restrict__ clsw, const float* __restrict__ clsb,
            float* __restrict__ out) {
    __shared__ alignas(16) float Tb[520];

    const int tid = threadIdx.x;

    // ---- in-CTA fused table build (32 unit-pairs x 16 floats) ----
    if (tid < 64) {
        const int n = tid;
        const int p = n >> 1, e = n & 1;
        float* d = Tb + p * 16;
        d[0 + e]  = 0.5f * Wix[2 * n];                               // A
        d[2 + e]  = 0.5f * Wix[2 * n + 1];                           // B
        d[4 + e]  = 0.5f * (Wih_b[n] + Wix_b[n] + bi[n]);            // C
        d[6 + e]  = 0.5f * WTt[n];                                   // D
        d[8 + e]  = 0.5f * WTx[2 * n];                               // E
        d[10 + e] = 0.5f * WTx[2 * n + 1];                           // F
        d[12 + e] = 0.5f * (WTh_b[n] + WTx_b[n] + WTt_b[n] + bT[n]); // G
        d[14 + e] = clsw[n];                                         // W
    }
    if (tid == 64) Tb[512] = clsb[0];
    __syncthreads();

    // ---- two rows per thread: r0 = base+tid, r1 = r0+128 (coalesced) ----
    const size_t base = (size_t)blockIdx.x * 256;
    const size_t r0 = base + tid;
    const size_t r1 = r0 + 128;

    const float* xa = X + r0 * 15 + 12;
    const float* xb = X + r1 * 15 + 12;
    const float x0a = xa[0], x1a = xa[1], dta = xa[2];
    const float x0b = xb[0], x1b = xb[1], dtb = xb[2];

    const u64 x0A = pk(x0a, x0a), x1A = pk(x1a, x1a);
    const u64 dtA = pk(dta, dta), dhA = pk(0.5f * dta, 0.5f * dta);
    const u64 x0B = pk(x0b, x0b), x1B = pk(x1b, x1b);
    const u64 dtB = pk(dtb, dtb), dhB = pk(0.5f * dtb, 0.5f * dtb);

    // t1 = z*P(s), s=z^2 on [0,4]: Chebyshev interpolant of tanh(sqrt(s))/sqrt(s)
    const u64 C0 = pk(0.998779f, 0.998779f);
    const u64 C1 = pk(-0.3172255f, -0.3172255f);
    const u64 C2 = pk(0.096472f, 0.096472f);
    const u64 C3 = pk(-0.0181456f, -0.0181456f);
    const u64 C4 = pk(0.0014467f, 0.0014467f);

    // h = tanh(0.5*m), m = uu*(1+t1) in [-2,2]: m*(A0 + A1 m^2 + A2 m^4)
    const u64 A0 = pk(0.4997350f, 0.4997350f);
    const u64 A1 = pk(-0.0397625f, -0.0397625f);
    const u64 A2 = pk(0.0025309f, 0.0025309f);

    u64 lgA = pk(0.0f, 0.0f);
    u64 lgB = pk(0.0f, 0.0f);

    const ulonglong2* TbU = (const ulonglong2*)Tb;

#pragma unroll
    for (int p = 0; p < 32; p++) {
        const ulonglong2 w0 = TbU[4 * p + 0];   // (Ap, Bp)
        const ulonglong2 w1 = TbU[4 * p + 1];   // (Cp, Dp)
        const ulonglong2 w2 = TbU[4 * p + 2];   // (Ep, Fp)
        const ulonglong2 w3 = TbU[4 * p + 3];   // (Gp, Wp)

        // ---- row A ----
        {
            const u64 z2 = fma2(w2.x, x0A, fma2(w2.y, x1A, fma2(w1.y, dtA, w3.x))); // 0.5*zT
            const u64 t2 = tanh2_mufu(z2);                      // MUFU
            const u64 z1 = fma2(w0.x, x0A, fma2(w0.y, x1A, w1.x));                  // 0.5*zi
            const u64 zc = clamp2_pm2(z1);                      // ALU
            const u64 sz = mul2(zc, zc);
            u64 pq = fma2(C4, sz, C3);
            pq = fma2(pq, sz, C2);
            pq = fma2(pq, sz, C1);
            pq = fma2(pq, sz, C0);
            const u64 t1 = mul2(pq, zc);                        // tanh(z1) on FMA
            const u64 ta = fma2(t2, dhA, dhA);                  // sig(zT)*dt
            const u64 uu = tanh2_mufu(ta);                      // MUFU
            const u64 m  = fma2(t1, uu, uu);                    // 2*cc, |m|<=2
            const u64 sm = mul2(m, m);
            u64 q = fma2(A2, sm, A1);
            q = fma2(q, sm, A0);
            lgA = fma2(mul2(q, m), w3.y, lgA);                  // h = q*m
        }
        // ---- row B ----
        {
            const u64 z2 = fma2(w2.x, x0B, fma2(w2.y, x1B, fma2(w1.y, dtB, w3.x)));
            const u64 t2 = tanh2_mufu(z2);
            const u64 z1 = fma2(w0.x, x0B, fma2(w0.y, x1B, w1.x));
            const u64 zc = clamp2_pm2(z1);
            const u64 sz = mul2(zc, zc);
            u64 pq = fma2(C4, sz, C3);
            pq = fma2(pq, sz, C2);
            pq = fma2(pq, sz, C1);
            pq = fma2(pq, sz, C0);
            const u64 t1 = mul2(pq, zc);
            const u64 ta = fma2(t2, dhB, dhB);
            const u64 uu = tanh2_mufu(ta);
            const u64 m  = fma2(t1, uu, uu);
            const u64 sm = mul2(m, m);
            u64 q = fma2(A2, sm, A1);
            q = fma2(q, sm, A0);
            lgB = fma2(mul2(q, m), w3.y, lgB);
        }
    }

    const float cb = Tb[512];
    float a0, a1, b0, b1;
    upk(a0, a1, lgA);
    upk(b0, b1, lgB);
    out[r0] = __fdividef(1.0f, 1.0f + __expf(-(a0 + a1 + cb)));
    out[r1] = __fdividef(1.0f, 1.0f + __expf(-(b0 + b1 + cb)));
}

extern "C" void kernel_launch(void* const* d_in, const int* in_sizes, int n_in,
                              void* d_out, int out_size) {
    const float* X      = (const float*)d_in[0];
    const float* Wih_b  = (const float*)d_in[7];
    const float* Wix_w  = (const float*)d_in[8];
    const float* Wix_b  = (const float*)d_in[9];
    const float* bi     = (const float*)d_in[10];
    const float* WTh_b  = (const float*)d_in[12];
    const float* WTx_w  = (const float*)d_in[13];
    const float* WTx_b  = (const float*)d_in[14];
    const float* WTt_w  = (const float*)d_in[15];
    const float* WTt_b  = (const float*)d_in[16];
    const float* bT     = (const float*)d_in[17];
    const float* cls_w  = (const float*)d_in[18];
    const float* cls_b  = (const float*)d_in[19];

    const int nrows  = in_sizes[0] / 15;
    const int blocks = nrows / 256;      // 2048 CTAs x 128 threads, 2 rows/thread

    stgn_kernel<<<blocks, 128>>>(
        X, Wix_w, Wix_b, Wih_b, bi,
        WTx_w, WTx_b, WTh_b, WTt_w, WTt_b, bT,
        cls_w, cls_b, (float*)d_out);
}